// round 2
// baseline (speedup 1.0000x reference)
#include <cuda_runtime.h>
#include <math.h>

#define B_   32
#define T_   256
#define D_   512
#define H_   8
#define DK_  64
#define TM_  1024
#define FF_  2048
#define NTOK (B_*T_)      // 8192
#define NMEM (B_*TM_)     // 32768

// ---------------- scratch (static device globals; no allocation allowed) ----
__device__ float g_x [NTOK*D_];
__device__ float g_n [NTOK*D_];
__device__ float g_q [NTOK*D_];
__device__ float g_k [NTOK*D_];
__device__ float g_v [NTOK*D_];
__device__ float g_a [NTOK*D_];
__device__ float g_f [NTOK*FF_];
__device__ float g_mk[NMEM*D_];
__device__ float g_mv[NMEM*D_];

// ---------------- embedding + positional encoding ---------------------------
__global__ void embed_kernel(const int* __restrict__ target,
                             const float* __restrict__ emb,
                             float* __restrict__ x)
{
    int idx = blockIdx.x * blockDim.x + threadIdx.x;
    if (idx >= NTOK * D_) return;
    int n = idx / D_, d = idx - n * D_;
    int t = n % T_;
    int tok = target[n];
    float val = emb[(size_t)tok * D_ + d] * 22.62741699796952f;  // sqrt(512)
    int p2 = (d >> 1) << 1;
    float freq = expf((float)p2 * (-9.210340371976184f / 512.0f)); // -ln(10000)/D
    float ang = (float)t * freq;
    val += (d & 1) ? cosf(ang) : sinf(ang);
    x[idx] = val;
}

// ---------------- layernorm: one warp per 512-wide row ----------------------
__global__ void ln_kernel(const float* __restrict__ in, float* __restrict__ out,
                          const float* __restrict__ g, const float* __restrict__ b,
                          int nrows)
{
    int warp = threadIdx.x >> 5;
    int row  = blockIdx.x * 8 + warp;
    if (row >= nrows) return;
    int lane = threadIdx.x & 31;
    const float4* p = (const float4*)(in + (size_t)row * D_);
    float4 v[4];
    float sum = 0.f;
#pragma unroll
    for (int c = 0; c < 4; c++) {
        v[c] = p[lane + 32 * c];
        sum += v[c].x + v[c].y + v[c].z + v[c].w;
    }
#pragma unroll
    for (int o = 16; o > 0; o >>= 1) sum += __shfl_xor_sync(0xffffffffu, sum, o);
    float mu = sum * (1.0f / 512.0f);
    float vs = 0.f;
#pragma unroll
    for (int c = 0; c < 4; c++) {
        float dx = v[c].x - mu, dy = v[c].y - mu, dz = v[c].z - mu, dw = v[c].w - mu;
        vs += dx * dx + dy * dy + dz * dz + dw * dw;
    }
#pragma unroll
    for (int o = 16; o > 0; o >>= 1) vs += __shfl_xor_sync(0xffffffffu, vs, o);
    float rstd = rsqrtf(vs * (1.0f / 512.0f) + 1e-6f);
    float4* op = (float4*)(out + (size_t)row * D_);
    const float4* g4 = (const float4*)g;
    const float4* b4 = (const float4*)b;
#pragma unroll
    for (int c = 0; c < 4; c++) {
        float4 gg = g4[lane + 32 * c], bb = b4[lane + 32 * c], r;
        r.x = (v[c].x - mu) * rstd * gg.x + bb.x;
        r.y = (v[c].y - mu) * rstd * gg.y + bb.y;
        r.z = (v[c].z - mu) * rstd * gg.z + bb.z;
        r.w = (v[c].w - mu) * rstd * gg.w + bb.w;
        op[lane + 32 * c] = r;
    }
}

// ---------------- generic GEMM: C = A(NxK) @ W(KxM) + bias [+resid] [relu] --
// 64x64 tile, BK=16, 256 threads, 4x4 micro-tile. All dims multiple of 64/16.
__global__ void gemm_kernel(const float* __restrict__ A, const float* __restrict__ W,
                            const float* __restrict__ bias, const float* __restrict__ resid,
                            float* __restrict__ C, int N, int K, int M, int relu)
{
    __shared__ float As[16][68];   // [k][m] transposed
    __shared__ float Ws[16][64];   // [k][n]
    int tid = threadIdx.x;
    int tx = tid & 15, ty = tid >> 4;
    int n0 = blockIdx.y * 64, m0 = blockIdx.x * 64;
    float acc[4][4] = {};
    int ak = tid & 15, am = tid >> 4;
    int wm = tid & 63, wk = tid >> 6;
    for (int k0 = 0; k0 < K; k0 += 16) {
#pragma unroll
        for (int l = 0; l < 4; l++)
            As[ak][am + l * 16] = A[(size_t)(n0 + am + l * 16) * K + k0 + ak];
#pragma unroll
        for (int l = 0; l < 4; l++)
            Ws[wk + l * 4][wm] = W[(size_t)(k0 + wk + l * 4) * M + m0 + wm];
        __syncthreads();
#pragma unroll
        for (int kk = 0; kk < 16; kk++) {
            float4 a4 = *(const float4*)&As[kk][ty * 4];
            float4 w4 = *(const float4*)&Ws[kk][tx * 4];
            float a[4] = {a4.x, a4.y, a4.z, a4.w};
            float w[4] = {w4.x, w4.y, w4.z, w4.w};
#pragma unroll
            for (int i = 0; i < 4; i++)
#pragma unroll
                for (int j = 0; j < 4; j++) acc[i][j] += a[i] * w[j];
        }
        __syncthreads();
    }
#pragma unroll
    for (int i = 0; i < 4; i++) {
        int r = n0 + ty * 4 + i;
#pragma unroll
        for (int j = 0; j < 4; j++) {
            int c = m0 + tx * 4 + j;
            float val = acc[i][j] + bias[c];
            if (resid) val += resid[(size_t)r * M + c];
            if (relu) val = fmaxf(val, 0.f);
            C[(size_t)r * M + c] = val;
        }
    }
}

// ---------------- fused flash attention -------------------------------------
// grid: (T_/64, B_*H_), 256 threads, dynamic smem = 3*64*68 floats (52 KB).
// Q rows: (b*T_+tq)*D_ + h*DK_; K/V rows: (b*Tk+tk)*D_ + h*DK_.
// Online softmax. NO causal chunk-skip: masked entries give exp(-1e9-m) which
// is exactly 0 for live rows and exactly 1 for fully-masked pad rows (uniform
// over all Tk positions) — matching JAX's where(mask, s, -1e9) semantics.
__global__ void flash_kernel(const float* __restrict__ Q,
                             const float* __restrict__ Kg,
                             const float* __restrict__ Vg,
                             float* __restrict__ O, int Tk,
                             const int* __restrict__ target, int causal)
{
    extern __shared__ float smem[];
    float* Qs = smem;                 // [d][q] 64x68
    float* Ks = smem + 64 * 68;       // [d][k] for K, then [k][d] for V
    float* Ps = smem + 2 * 64 * 68;   // [k][q] 64x68

    int tid = threadIdx.x;
    int tx = tid & 15, ty = tid >> 4;
    int z = blockIdx.y;
    int b = z >> 3, h = z & 7;
    int tq0 = blockIdx.x * 64;

    // load Q tile: Qs[d][q]
    {
        int c = tid & 63, r0 = tid >> 6;
#pragma unroll
        for (int p = 0; p < 16; p++) {
            int r = r0 + p * 4;
            Qs[c * 68 + r] = Q[(size_t)(b * T_ + tq0 + r) * D_ + h * DK_ + c];
        }
    }

    float m[4], l[4], o[4][4];
#pragma unroll
    for (int i = 0; i < 4; i++) {
        m[i] = -1e30f; l[i] = 0.f;
#pragma unroll
        for (int j = 0; j < 4; j++) o[i][j] = 0.f;
    }
    bool rowok[4];
#pragma unroll
    for (int i = 0; i < 4; i++) {
        int tq = tq0 + ty * 4 + i;
        rowok[i] = causal ? (target[b * T_ + tq] != 0) : true;
    }

    for (int kt0 = 0; kt0 < Tk; kt0 += 64) {
        // load K chunk: Ks[d][k]
        {
            int c = tid & 63, r0 = tid >> 6;
#pragma unroll
            for (int p = 0; p < 16; p++) {
                int r = r0 + p * 4;
                Ks[c * 68 + r] = Kg[(size_t)(b * Tk + kt0 + r) * D_ + h * DK_ + c];
            }
        }
        __syncthreads();

        // S = Q K^T (micro 4x4 over d)
        float s[4][4] = {};
#pragma unroll 8
        for (int d = 0; d < 64; d++) {
            float4 a4 = *(const float4*)&Qs[d * 68 + ty * 4];
            float4 k4 = *(const float4*)&Ks[d * 68 + tx * 4];
            float a[4] = {a4.x, a4.y, a4.z, a4.w};
            float kk[4] = {k4.x, k4.y, k4.z, k4.w};
#pragma unroll
            for (int i = 0; i < 4; i++)
#pragma unroll
                for (int j = 0; j < 4; j++) s[i][j] += a[i] * kk[j];
        }

        // scale + mask + online softmax update
        float alpha[4];
#pragma unroll
        for (int i = 0; i < 4; i++) {
            int tq = tq0 + ty * 4 + i;
            float rm = -1e30f;
#pragma unroll
            for (int j = 0; j < 4; j++) {
                int tk = kt0 + tx * 4 + j;
                bool ok = !causal || (rowok[i] && tk <= tq);
                s[i][j] = ok ? s[i][j] * 0.125f : -1e9f;
                rm = fmaxf(rm, s[i][j]);
            }
#pragma unroll
            for (int off = 1; off < 16; off <<= 1)
                rm = fmaxf(rm, __shfl_xor_sync(0xffffffffu, rm, off));
            float mnew = fmaxf(m[i], rm);
            alpha[i] = expf(m[i] - mnew);
            m[i] = mnew;
            float rs = 0.f;
#pragma unroll
            for (int j = 0; j < 4; j++) {
                s[i][j] = expf(s[i][j] - mnew);   // now p
                rs += s[i][j];
            }
#pragma unroll
            for (int off = 1; off < 16; off <<= 1)
                rs += __shfl_xor_sync(0xffffffffu, rs, off);
            l[i] = l[i] * alpha[i] + rs;
#pragma unroll
            for (int j = 0; j < 4; j++) o[i][j] *= alpha[i];
        }

        // stage P: Ps[k][q]
#pragma unroll
        for (int i = 0; i < 4; i++)
#pragma unroll
            for (int j = 0; j < 4; j++)
                Ps[(tx * 4 + j) * 68 + ty * 4 + i] = s[i][j];
        __syncthreads();   // all reads of Ks done; Ps visible

        // load V chunk into Ks region: Vs[k][d]
        {
            int c = tid & 63, r0 = tid >> 6;
#pragma unroll
            for (int p = 0; p < 16; p++) {
                int r = r0 + p * 4;
                Ks[r * 68 + c] = Vg[(size_t)(b * Tk + kt0 + r) * D_ + h * DK_ + c];
            }
        }
        __syncthreads();

        // O += P V (micro 4x4 over k)
#pragma unroll 8
        for (int kk = 0; kk < 64; kk++) {
            float4 p4 = *(const float4*)&Ps[kk * 68 + ty * 4];
            float4 v4 = *(const float4*)&Ks[kk * 68 + tx * 4];
            float pp[4] = {p4.x, p4.y, p4.z, p4.w};
            float vv[4] = {v4.x, v4.y, v4.z, v4.w};
#pragma unroll
            for (int i = 0; i < 4; i++)
#pragma unroll
                for (int j = 0; j < 4; j++) o[i][j] += pp[i] * vv[j];
        }
        __syncthreads();   // before next iter overwrites Ks/Ps
    }

#pragma unroll
    for (int i = 0; i < 4; i++) {
        float inv = 1.0f / l[i];
        int tq = tq0 + ty * 4 + i;
#pragma unroll
        for (int j = 0; j < 4; j++)
            O[(size_t)(b * T_ + tq) * D_ + h * DK_ + tx * 4 + j] = o[i][j] * inv;
    }
}

// ---------------- host orchestration ----------------------------------------
extern "C" void kernel_launch(void* const* d_in, const int* in_sizes, int n_in,
                              void* d_out, int out_size)
{
    (void)in_sizes; (void)n_in; (void)out_size;
    float *x, *nb, *q, *k, *v, *a, *f, *mk, *mv;
    cudaGetSymbolAddress((void**)&x,  g_x);
    cudaGetSymbolAddress((void**)&nb, g_n);
    cudaGetSymbolAddress((void**)&q,  g_q);
    cudaGetSymbolAddress((void**)&k,  g_k);
    cudaGetSymbolAddress((void**)&v,  g_v);
    cudaGetSymbolAddress((void**)&a,  g_a);
    cudaGetSymbolAddress((void**)&f,  g_f);
    cudaGetSymbolAddress((void**)&mk, g_mk);
    cudaGetSymbolAddress((void**)&mv, g_mv);

    const int FLASH_SMEM = 3 * 64 * 68 * 4;   // 52224 B
    static int smem_set = 0;
    if (!smem_set) {
        cudaFuncSetAttribute(flash_kernel, cudaFuncAttributeMaxDynamicSharedMemorySize, FLASH_SMEM);
        smem_set = 1;
    }

    // setup_inputs() dict order
    const int*   target = (const int*)  d_in[0];
    const float* memory = (const float*)d_in[1];
    const float* emb    = (const float*)d_in[2];
    const float* ln_g   = (const float*)d_in[3];
    const float* ln_b   = (const float*)d_in[4];
    const float* ff_w1  = (const float*)d_in[5];
    const float* ff_b1  = (const float*)d_in[6];
    const float* ff_w2  = (const float*)d_in[7];
    const float* ff_b2  = (const float*)d_in[8];
    const float* sa_wq  = (const float*)d_in[9];
    const float* sa_bq  = (const float*)d_in[10];
    const float* ca_wq  = (const float*)d_in[11];
    const float* ca_bq  = (const float*)d_in[12];
    const float* sa_wk  = (const float*)d_in[13];
    const float* sa_bk  = (const float*)d_in[14];
    const float* ca_wk  = (const float*)d_in[15];
    const float* ca_bk  = (const float*)d_in[16];
    const float* sa_wv  = (const float*)d_in[17];
    const float* sa_bv  = (const float*)d_in[18];
    const float* ca_wv  = (const float*)d_in[19];
    const float* ca_bv  = (const float*)d_in[20];
    const float* sa_wo  = (const float*)d_in[21];
    const float* sa_bo  = (const float*)d_in[22];
    const float* ca_wo  = (const float*)d_in[23];
    const float* ca_bo  = (const float*)d_in[24];

    embed_kernel<<<(NTOK * D_ + 255) / 256, 256>>>(target, emb, x);

    // cross-attn K/V of memory: computed ONCE (shared weights, static memory)
    gemm_kernel<<<dim3(D_ / 64, NMEM / 64), 256>>>(memory, ca_wk, ca_bk, nullptr, mk, NMEM, D_, D_, 0);
    gemm_kernel<<<dim3(D_ / 64, NMEM / 64), 256>>>(memory, ca_wv, ca_bv, nullptr, mv, NMEM, D_, D_, 0);

    dim3 gProj(D_ / 64, NTOK / 64);   // (8,128)
    dim3 gFF1 (FF_ / 64, NTOK / 64);  // (32,128)
    dim3 gFlash(T_ / 64, B_ * H_);    // (4,256)

    for (int st = 0; st < 3; st++) {
        // ---- self attention ----
        ln_kernel<<<NTOK / 8, 256>>>(x, nb, ln_g, ln_b, NTOK);
        gemm_kernel<<<gProj, 256>>>(nb, sa_wq, sa_bq, nullptr, q, NTOK, D_, D_, 0);
        gemm_kernel<<<gProj, 256>>>(nb, sa_wk, sa_bk, nullptr, k, NTOK, D_, D_, 0);
        gemm_kernel<<<gProj, 256>>>(nb, sa_wv, sa_bv, nullptr, v, NTOK, D_, D_, 0);
        flash_kernel<<<gFlash, 256, FLASH_SMEM>>>(q, k, v, a, T_, target, 1);
        gemm_kernel<<<gProj, 256>>>(a, sa_wo, sa_bo, x, x, NTOK, D_, D_, 0);

        // ---- cross attention ----
        ln_kernel<<<NTOK / 8, 256>>>(x, nb, ln_g, ln_b, NTOK);
        gemm_kernel<<<gProj, 256>>>(nb, ca_wq, ca_bq, nullptr, q, NTOK, D_, D_, 0);
        flash_kernel<<<gFlash, 256, FLASH_SMEM>>>(q, mk, mv, a, TM_, nullptr, 0);
        gemm_kernel<<<gProj, 256>>>(a, ca_wo, ca_bo, x, x, NTOK, D_, D_, 0);

        // ---- feed forward ----
        ln_kernel<<<NTOK / 8, 256>>>(x, nb, ln_g, ln_b, NTOK);
        gemm_kernel<<<gFF1, 256>>>(nb, ff_w1, ff_b1, nullptr, f, NTOK, D_, FF_, 1);
        gemm_kernel<<<gProj, 256>>>(f, ff_w2, ff_b2, x, x, NTOK, FF_, D_, 0);
    }

    ln_kernel<<<NTOK / 8, 256>>>(x, (float*)d_out, ln_g, ln_b, NTOK);
}

// round 4
// speedup vs baseline: 2.1018x; 2.1018x over previous
#include <cuda_runtime.h>
#include <math.h>
#include <stdint.h>

#define B_   32
#define T_   256
#define D_   512
#define H_   8
#define DK_  64
#define TM_  1024
#define FF_  2048
#define NTOK (B_*T_)      // 8192
#define NMEM (B_*TM_)     // 32768

// ---------------- scratch (static device globals; no allocation allowed) ----
__device__ float g_x [NTOK*D_];
__device__ float g_n [NTOK*D_];
__device__ float g_q [NTOK*D_];
__device__ float g_k [NTOK*D_];
__device__ float g_v [NTOK*D_];
__device__ float g_a [NTOK*D_];
__device__ float g_f [NTOK*FF_];
__device__ float g_mk[NMEM*D_];
__device__ float g_mv[NMEM*D_];

// ---------------- embedding + positional encoding ---------------------------
__global__ void embed_kernel(const int* __restrict__ target,
                             const float* __restrict__ emb,
                             float* __restrict__ x)
{
    int idx = blockIdx.x * blockDim.x + threadIdx.x;
    if (idx >= NTOK * D_) return;
    int n = idx / D_, d = idx - n * D_;
    int t = n % T_;
    int tok = target[n];
    float val = emb[(size_t)tok * D_ + d] * 22.62741699796952f;  // sqrt(512)
    int p2 = (d >> 1) << 1;
    float freq = expf((float)p2 * (-9.210340371976184f / 512.0f)); // -ln(10000)/D
    float ang = (float)t * freq;
    val += (d & 1) ? cosf(ang) : sinf(ang);
    x[idx] = val;
}

// ---------------- layernorm: one warp per 512-wide row ----------------------
__global__ void ln_kernel(const float* __restrict__ in, float* __restrict__ out,
                          const float* __restrict__ g, const float* __restrict__ b,
                          int nrows)
{
    int warp = threadIdx.x >> 5;
    int row  = blockIdx.x * 8 + warp;
    if (row >= nrows) return;
    int lane = threadIdx.x & 31;
    const float4* p = (const float4*)(in + (size_t)row * D_);
    float4 v[4];
    float sum = 0.f;
#pragma unroll
    for (int c = 0; c < 4; c++) {
        v[c] = p[lane + 32 * c];
        sum += v[c].x + v[c].y + v[c].z + v[c].w;
    }
#pragma unroll
    for (int o = 16; o > 0; o >>= 1) sum += __shfl_xor_sync(0xffffffffu, sum, o);
    float mu = sum * (1.0f / 512.0f);
    float vs = 0.f;
#pragma unroll
    for (int c = 0; c < 4; c++) {
        float dx = v[c].x - mu, dy = v[c].y - mu, dz = v[c].z - mu, dw = v[c].w - mu;
        vs += dx * dx + dy * dy + dz * dz + dw * dw;
    }
#pragma unroll
    for (int o = 16; o > 0; o >>= 1) vs += __shfl_xor_sync(0xffffffffu, vs, o);
    float rstd = rsqrtf(vs * (1.0f / 512.0f) + 1e-6f);
    float4* op = (float4*)(out + (size_t)row * D_);
    const float4* g4 = (const float4*)g;
    const float4* b4 = (const float4*)b;
#pragma unroll
    for (int c = 0; c < 4; c++) {
        float4 gg = g4[lane + 32 * c], bb = b4[lane + 32 * c], r;
        r.x = (v[c].x - mu) * rstd * gg.x + bb.x;
        r.y = (v[c].y - mu) * rstd * gg.y + bb.y;
        r.z = (v[c].z - mu) * rstd * gg.z + bb.z;
        r.w = (v[c].w - mu) * rstd * gg.w + bb.w;
        op[lane + 32 * c] = r;
    }
}

// ---------------- tf32 tensor-core GEMM -------------------------------------
__device__ __forceinline__ float tf32r(float x) {
    uint32_t u;
    asm("cvt.rna.tf32.f32 %0, %1;" : "=r"(u) : "f"(x));
    return __uint_as_float(u);
}

__device__ __forceinline__ void mma_tf32(float* c, const uint32_t* a, const uint32_t* b) {
    asm volatile(
        "mma.sync.aligned.m16n8k8.row.col.f32.tf32.tf32.f32 "
        "{%0,%1,%2,%3}, {%4,%5,%6,%7}, {%8,%9}, {%0,%1,%2,%3};\n"
        : "+f"(c[0]), "+f"(c[1]), "+f"(c[2]), "+f"(c[3])
        : "r"(a[0]), "r"(a[1]), "r"(a[2]), "r"(a[3]), "r"(b[0]), "r"(b[1]));
}

// C[M,N] = A[M,K] @ W[K,N] + bias [+resid] [relu]
// CTA tile 128x128, KB=32, 256 threads (8 warps of 64x32), tf32 mma.
// M % 128 == 0, N % 128 == 0, K % 32 == 0.
__global__ __launch_bounds__(256, 2) void gemm_tc(
    const float* __restrict__ A, const float* __restrict__ W,
    const float* __restrict__ bias, const float* __restrict__ resid,
    float* __restrict__ C, int M, int K, int N, int relu)
{
    __shared__ float As[128][36];   // stride 36 == 4 (mod 32): conflict-free frags
    __shared__ float Bs[32][136];   // stride 136 == 8 (mod 32): conflict-free frags
    int tid = threadIdx.x;
    int lane = tid & 31, warp = tid >> 5;
    int wm = (warp >> 2) * 64;      // warp m-offset: 0 / 64
    int wn = (warp & 3) * 32;       // warp n-offset: 0..96
    size_t m0 = (size_t)blockIdx.y * 128, n0 = (size_t)blockIdx.x * 128;

    float acc[4][4][4];
#pragma unroll
    for (int mi = 0; mi < 4; mi++)
#pragma unroll
        for (int ni = 0; ni < 4; ni++)
#pragma unroll
            for (int r2 = 0; r2 < 4; r2++) acc[mi][ni][r2] = 0.f;

    int arow = tid >> 1, acq = (tid & 1) * 16;   // A: 2 thr/row, 4 float4 each
    int brow = tid >> 3, bcq = (tid & 7) * 4;    // B: 8 thr/row, 4 float4 each (stride 32)
    int r = lane >> 2, cg = lane & 3;

    for (int k0 = 0; k0 < K; k0 += 32) {
#pragma unroll
        for (int j = 0; j < 4; j++) {
            float4 a4 = *(const float4*)(A + (m0 + arow) * K + k0 + acq + 4 * j);
            a4.x = tf32r(a4.x); a4.y = tf32r(a4.y); a4.z = tf32r(a4.z); a4.w = tf32r(a4.w);
            *(float4*)&As[arow][acq + 4 * j] = a4;
        }
#pragma unroll
        for (int j = 0; j < 4; j++) {
            float4 b4 = *(const float4*)(W + (size_t)(k0 + brow) * N + n0 + bcq + 32 * j);
            b4.x = tf32r(b4.x); b4.y = tf32r(b4.y); b4.z = tf32r(b4.z); b4.w = tf32r(b4.w);
            *(float4*)&Bs[brow][bcq + 32 * j] = b4;
        }
        __syncthreads();
#pragma unroll
        for (int ks = 0; ks < 4; ks++) {
            int kb = ks * 8;
            uint32_t af[4][4], bf[4][2];
#pragma unroll
            for (int mi = 0; mi < 4; mi++) {
                int rb = wm + mi * 16;
                af[mi][0] = __float_as_uint(As[rb + r][kb + cg]);
                af[mi][1] = __float_as_uint(As[rb + 8 + r][kb + cg]);
                af[mi][2] = __float_as_uint(As[rb + r][kb + 4 + cg]);
                af[mi][3] = __float_as_uint(As[rb + 8 + r][kb + 4 + cg]);
            }
#pragma unroll
            for (int ni = 0; ni < 4; ni++) {
                bf[ni][0] = __float_as_uint(Bs[kb + cg][wn + ni * 8 + r]);
                bf[ni][1] = __float_as_uint(Bs[kb + 4 + cg][wn + ni * 8 + r]);
            }
#pragma unroll
            for (int mi = 0; mi < 4; mi++)
#pragma unroll
                for (int ni = 0; ni < 4; ni++)
                    mma_tf32(acc[mi][ni], af[mi], bf[ni]);
        }
        __syncthreads();
    }

    // epilogue: c0,c1 at (row, 2c/2c+1), c2,c3 at (row+8, ...)
    int c2 = (lane & 3) * 2;
#pragma unroll
    for (int mi = 0; mi < 4; mi++) {
#pragma unroll
        for (int ni = 0; ni < 4; ni++) {
            size_t gm = m0 + wm + mi * 16 + r;
            size_t gn = n0 + wn + ni * 8 + c2;
            float b0v = bias[gn], b1v = bias[gn + 1];
            float v0 = acc[mi][ni][0] + b0v, v1 = acc[mi][ni][1] + b1v;
            float v2 = acc[mi][ni][2] + b0v, v3 = acc[mi][ni][3] + b1v;
            if (resid) {
                const float2 r0 = *(const float2*)(resid + gm * N + gn);
                const float2 r1 = *(const float2*)(resid + (gm + 8) * N + gn);
                v0 += r0.x; v1 += r0.y; v2 += r1.x; v3 += r1.y;
            }
            if (relu) {
                v0 = fmaxf(v0, 0.f); v1 = fmaxf(v1, 0.f);
                v2 = fmaxf(v2, 0.f); v3 = fmaxf(v3, 0.f);
            }
            *(float2*)(C + gm * N + gn) = make_float2(v0, v1);
            *(float2*)(C + (gm + 8) * N + gn) = make_float2(v2, v3);
        }
    }
}

// ---------------- fused flash attention (fp32, unchanged) -------------------
__global__ void flash_kernel(const float* __restrict__ Q,
                             const float* __restrict__ Kg,
                             const float* __restrict__ Vg,
                             float* __restrict__ O, int Tk,
                             const int* __restrict__ target, int causal)
{
    extern __shared__ float smem[];
    float* Qs = smem;                 // [d][q] 64x68
    float* Ks = smem + 64 * 68;       // [d][k] for K, then [k][d] for V
    float* Ps = smem + 2 * 64 * 68;   // [k][q] 64x68

    int tid = threadIdx.x;
    int tx = tid & 15, ty = tid >> 4;
    int z = blockIdx.y;
    int b = z >> 3, h = z & 7;
    int tq0 = blockIdx.x * 64;

    {
        int c = tid & 63, r0 = tid >> 6;
#pragma unroll
        for (int p = 0; p < 16; p++) {
            int r = r0 + p * 4;
            Qs[c * 68 + r] = Q[(size_t)(b * T_ + tq0 + r) * D_ + h * DK_ + c];
        }
    }

    float m[4], l[4], o[4][4];
#pragma unroll
    for (int i = 0; i < 4; i++) {
        m[i] = -1e30f; l[i] = 0.f;
#pragma unroll
        for (int j = 0; j < 4; j++) o[i][j] = 0.f;
    }
    bool rowok[4];
#pragma unroll
    for (int i = 0; i < 4; i++) {
        int tq = tq0 + ty * 4 + i;
        rowok[i] = causal ? (target[b * T_ + tq] != 0) : true;
    }

    for (int kt0 = 0; kt0 < Tk; kt0 += 64) {
        {
            int c = tid & 63, r0 = tid >> 6;
#pragma unroll
            for (int p = 0; p < 16; p++) {
                int r = r0 + p * 4;
                Ks[c * 68 + r] = Kg[(size_t)(b * Tk + kt0 + r) * D_ + h * DK_ + c];
            }
        }
        __syncthreads();

        float s[4][4] = {};
#pragma unroll 8
        for (int d = 0; d < 64; d++) {
            float4 a4 = *(const float4*)&Qs[d * 68 + ty * 4];
            float4 k4 = *(const float4*)&Ks[d * 68 + tx * 4];
            float a[4] = {a4.x, a4.y, a4.z, a4.w};
            float kk[4] = {k4.x, k4.y, k4.z, k4.w};
#pragma unroll
            for (int i = 0; i < 4; i++)
#pragma unroll
                for (int j = 0; j < 4; j++) s[i][j] += a[i] * kk[j];
        }

        float alpha[4];
#pragma unroll
        for (int i = 0; i < 4; i++) {
            int tq = tq0 + ty * 4 + i;
            float rm = -1e30f;
#pragma unroll
            for (int j = 0; j < 4; j++) {
                int tk = kt0 + tx * 4 + j;
                bool ok = !causal || (rowok[i] && tk <= tq);
                s[i][j] = ok ? s[i][j] * 0.125f : -1e9f;
                rm = fmaxf(rm, s[i][j]);
            }
#pragma unroll
            for (int off = 1; off < 16; off <<= 1)
                rm = fmaxf(rm, __shfl_xor_sync(0xffffffffu, rm, off));
            float mnew = fmaxf(m[i], rm);
            alpha[i] = expf(m[i] - mnew);
            m[i] = mnew;
            float rs = 0.f;
#pragma unroll
            for (int j = 0; j < 4; j++) {
                s[i][j] = expf(s[i][j] - mnew);
                rs += s[i][j];
            }
#pragma unroll
            for (int off = 1; off < 16; off <<= 1)
                rs += __shfl_xor_sync(0xffffffffu, rs, off);
            l[i] = l[i] * alpha[i] + rs;
#pragma unroll
            for (int j = 0; j < 4; j++) o[i][j] *= alpha[i];
        }

#pragma unroll
        for (int i = 0; i < 4; i++)
#pragma unroll
            for (int j = 0; j < 4; j++)
                Ps[(tx * 4 + j) * 68 + ty * 4 + i] = s[i][j];
        __syncthreads();

        {
            int c = tid & 63, r0 = tid >> 6;
#pragma unroll
            for (int p = 0; p < 16; p++) {
                int r = r0 + p * 4;
                Ks[r * 68 + c] = Vg[(size_t)(b * Tk + kt0 + r) * D_ + h * DK_ + c];
            }
        }
        __syncthreads();

#pragma unroll 8
        for (int kk = 0; kk < 64; kk++) {
            float4 p4 = *(const float4*)&Ps[kk * 68 + ty * 4];
            float4 v4 = *(const float4*)&Ks[kk * 68 + tx * 4];
            float pp[4] = {p4.x, p4.y, p4.z, p4.w};
            float vv[4] = {v4.x, v4.y, v4.z, v4.w};
#pragma unroll
            for (int i = 0; i < 4; i++)
#pragma unroll
                for (int j = 0; j < 4; j++) o[i][j] += pp[i] * vv[j];
        }
        __syncthreads();
    }

#pragma unroll
    for (int i = 0; i < 4; i++) {
        float inv = 1.0f / l[i];
        int tq = tq0 + ty * 4 + i;
#pragma unroll
        for (int j = 0; j < 4; j++)
            O[(size_t)(b * T_ + tq) * D_ + h * DK_ + tx * 4 + j] = o[i][j] * inv;
    }
}

// ---------------- host orchestration ----------------------------------------
extern "C" void kernel_launch(void* const* d_in, const int* in_sizes, int n_in,
                              void* d_out, int out_size)
{
    (void)in_sizes; (void)n_in; (void)out_size;
    float *x, *nb, *q, *k, *v, *a, *f, *mk, *mv;
    cudaGetSymbolAddress((void**)&x,  g_x);
    cudaGetSymbolAddress((void**)&nb, g_n);
    cudaGetSymbolAddress((void**)&q,  g_q);
    cudaGetSymbolAddress((void**)&k,  g_k);
    cudaGetSymbolAddress((void**)&v,  g_v);
    cudaGetSymbolAddress((void**)&a,  g_a);
    cudaGetSymbolAddress((void**)&f,  g_f);
    cudaGetSymbolAddress((void**)&mk, g_mk);
    cudaGetSymbolAddress((void**)&mv, g_mv);

    const int FLASH_SMEM = 3 * 64 * 68 * 4;   // 52224 B
    static int smem_set = 0;
    if (!smem_set) {
        cudaFuncSetAttribute(flash_kernel, cudaFuncAttributeMaxDynamicSharedMemorySize, FLASH_SMEM);
        smem_set = 1;
    }

    // setup_inputs() dict order (verified R2: rel_err 1.2e-6)
    const int*   target = (const int*)  d_in[0];
    const float* memory = (const float*)d_in[1];
    const float* emb    = (const float*)d_in[2];
    const float* ln_g   = (const float*)d_in[3];
    const float* ln_b   = (const float*)d_in[4];
    const float* ff_w1  = (const float*)d_in[5];
    const float* ff_b1  = (const float*)d_in[6];
    const float* ff_w2  = (const float*)d_in[7];
    const float* ff_b2  = (const float*)d_in[8];
    const float* sa_wq  = (const float*)d_in[9];
    const float* sa_bq  = (const float*)d_in[10];
    const float* ca_wq  = (const float*)d_in[11];
    const float* ca_bq  = (const float*)d_in[12];
    const float* sa_wk  = (const float*)d_in[13];
    const float* sa_bk  = (const float*)d_in[14];
    const float* ca_wk  = (const float*)d_in[15];
    const float* ca_bk  = (const float*)d_in[16];
    const float* sa_wv  = (const float*)d_in[17];
    const float* sa_bv  = (const float*)d_in[18];
    const float* ca_wv  = (const float*)d_in[19];
    const float* ca_bv  = (const float*)d_in[20];
    const float* sa_wo  = (const float*)d_in[21];
    const float* sa_bo  = (const float*)d_in[22];
    const float* ca_wo  = (const float*)d_in[23];
    const float* ca_bo  = (const float*)d_in[24];

    embed_kernel<<<(NTOK * D_ + 255) / 256, 256>>>(target, emb, x);

    // cross-attn K/V of memory: computed ONCE (shared weights, static memory)
    gemm_tc<<<dim3(D_ / 128, NMEM / 128), 256>>>(memory, ca_wk, ca_bk, nullptr, mk, NMEM, D_, D_, 0);
    gemm_tc<<<dim3(D_ / 128, NMEM / 128), 256>>>(memory, ca_wv, ca_bv, nullptr, mv, NMEM, D_, D_, 0);

    dim3 gProj(D_ / 128, NTOK / 128);   // (4,64)
    dim3 gFF1 (FF_ / 128, NTOK / 128);  // (16,64)
    dim3 gFlash(T_ / 64, B_ * H_);      // (4,256)

    for (int st = 0; st < 3; st++) {
        // ---- self attention ----
        ln_kernel<<<NTOK / 8, 256>>>(x, nb, ln_g, ln_b, NTOK);
        gemm_tc<<<gProj, 256>>>(nb, sa_wq, sa_bq, nullptr, q, NTOK, D_, D_, 0);
        gemm_tc<<<gProj, 256>>>(nb, sa_wk, sa_bk, nullptr, k, NTOK, D_, D_, 0);
        gemm_tc<<<gProj, 256>>>(nb, sa_wv, sa_bv, nullptr, v, NTOK, D_, D_, 0);
        flash_kernel<<<gFlash, 256, FLASH_SMEM>>>(q, k, v, a, T_, target, 1);
        gemm_tc<<<gProj, 256>>>(a, sa_wo, sa_bo, x, x, NTOK, D_, D_, 0);

        // ---- cross attention ----
        ln_kernel<<<NTOK / 8, 256>>>(x, nb, ln_g, ln_b, NTOK);
        gemm_tc<<<gProj, 256>>>(nb, ca_wq, ca_bq, nullptr, q, NTOK, D_, D_, 0);
        flash_kernel<<<gFlash, 256, FLASH_SMEM>>>(q, mk, mv, a, TM_, nullptr, 0);
        gemm_tc<<<gProj, 256>>>(a, ca_wo, ca_bo, x, x, NTOK, D_, D_, 0);

        // ---- feed forward ----
        ln_kernel<<<NTOK / 8, 256>>>(x, nb, ln_g, ln_b, NTOK);
        gemm_tc<<<gFF1, 256>>>(nb, ff_w1, ff_b1, nullptr, f, NTOK, D_, FF_, 1);
        gemm_tc<<<gProj, 256>>>(f, ff_w2, ff_b2, x, x, NTOK, FF_, D_, 0);
    }

    ln_kernel<<<NTOK / 8, 256>>>(x, (float*)d_out, ln_g, ln_b, NTOK);
}

// round 12
// speedup vs baseline: 2.8745x; 1.3677x over previous
#include <cuda_runtime.h>
#include <math.h>
#include <stdint.h>

#define B_   32
#define T_   256
#define D_   512
#define H_   8
#define DK_  64
#define TM_  1024
#define FF_  2048
#define NTOK (B_*T_)      // 8192
#define NMEM (B_*TM_)     // 32768

// ---------------- scratch (static device globals; no allocation allowed) ----
__device__ float g_x [NTOK*D_];
__device__ float g_n [NTOK*D_];
__device__ float g_q [NTOK*D_];
__device__ float g_k [NTOK*D_];
__device__ float g_v [NTOK*D_];
__device__ float g_a [NTOK*D_];
__device__ float g_f [NTOK*FF_];
__device__ float g_mk[NMEM*D_];
__device__ float g_mv[NMEM*D_];

// ---------------- small helpers ---------------------------------------------
__device__ __forceinline__ float tf32r(float x) {
    uint32_t u;
    asm("cvt.rna.tf32.f32 %0, %1;" : "=r"(u) : "f"(x));
    return __uint_as_float(u);
}
__device__ __forceinline__ uint32_t tf32u(float x) {
    uint32_t u;
    asm("cvt.rna.tf32.f32 %0, %1;" : "=r"(u) : "f"(x));
    return u;
}
__device__ __forceinline__ void mma_tf32(float* c, const uint32_t* a, const uint32_t* b) {
    asm volatile(
        "mma.sync.aligned.m16n8k8.row.col.f32.tf32.tf32.f32 "
        "{%0,%1,%2,%3}, {%4,%5,%6,%7}, {%8,%9}, {%0,%1,%2,%3};\n"
        : "+f"(c[0]), "+f"(c[1]), "+f"(c[2]), "+f"(c[3])
        : "r"(a[0]), "r"(a[1]), "r"(a[2]), "r"(a[3]), "r"(b[0]), "r"(b[1]));
}
__device__ __forceinline__ uint32_t sptr(const void* p) {
    return (uint32_t)__cvta_generic_to_shared(p);
}
__device__ __forceinline__ void cpa16(uint32_t dst, const void* src) {
    asm volatile("cp.async.cg.shared.global [%0], [%1], 16;\n"
                 :: "r"(dst), "l"(src) : "memory");
}

// ---------------- embedding + positional encoding ---------------------------
__global__ void embed_kernel(const int* __restrict__ target,
                             const float* __restrict__ emb,
                             float* __restrict__ x)
{
    int idx = blockIdx.x * blockDim.x + threadIdx.x;
    if (idx >= NTOK * D_) return;
    int n = idx / D_, d = idx - n * D_;
    int t = n % T_;
    int tok = target[n];
    float val = emb[(size_t)tok * D_ + d] * 22.62741699796952f;  // sqrt(512)
    int p2 = (d >> 1) << 1;
    float freq = expf((float)p2 * (-9.210340371976184f / 512.0f)); // -ln(10000)/D
    float ang = (float)t * freq;
    val += (d & 1) ? cosf(ang) : sinf(ang);
    x[idx] = val;
}

// ---------------- layernorm: one warp per 512-wide row ----------------------
__global__ void ln_kernel(const float* __restrict__ in, float* __restrict__ out,
                          const float* __restrict__ g, const float* __restrict__ b,
                          int nrows)
{
    int warp = threadIdx.x >> 5;
    int row  = blockIdx.x * 8 + warp;
    if (row >= nrows) return;
    int lane = threadIdx.x & 31;
    const float4* p = (const float4*)(in + (size_t)row * D_);
    float4 v[4];
    float sum = 0.f;
#pragma unroll
    for (int c = 0; c < 4; c++) {
        v[c] = p[lane + 32 * c];
        sum += v[c].x + v[c].y + v[c].z + v[c].w;
    }
#pragma unroll
    for (int o = 16; o > 0; o >>= 1) sum += __shfl_xor_sync(0xffffffffu, sum, o);
    float mu = sum * (1.0f / 512.0f);
    float vs = 0.f;
#pragma unroll
    for (int c = 0; c < 4; c++) {
        float dx = v[c].x - mu, dy = v[c].y - mu, dz = v[c].z - mu, dw = v[c].w - mu;
        vs += dx * dx + dy * dy + dz * dz + dw * dw;
    }
#pragma unroll
    for (int o = 16; o > 0; o >>= 1) vs += __shfl_xor_sync(0xffffffffu, vs, o);
    float rstd = rsqrtf(vs * (1.0f / 512.0f) + 1e-6f);
    float4* op = (float4*)(out + (size_t)row * D_);
    const float4* g4 = (const float4*)g;
    const float4* b4 = (const float4*)b;
#pragma unroll
    for (int c = 0; c < 4; c++) {
        float4 gg = g4[lane + 32 * c], bb = b4[lane + 32 * c], r;
        r.x = (v[c].x - mu) * rstd * gg.x + bb.x;
        r.y = (v[c].y - mu) * rstd * gg.y + bb.y;
        r.z = (v[c].z - mu) * rstd * gg.z + bb.z;
        r.w = (v[c].w - mu) * rstd * gg.w + bb.w;
        op[lane + 32 * c] = r;
    }
}

// ---------------- tf32 tensor-core GEMM, cp.async double-buffered -----------
// C[M,N] = A[M,K] @ W[K,N] + bias [+resid] [relu]
// CTA tile 128x128, KB=32, 256 threads (8 warps of 64x32).
// dyn smem: 2 stages of As[128][36] + Bs[32][136] = 71680 B.
#define GEMM_SMEM (2*(128*36 + 32*136)*4)
__global__ __launch_bounds__(256, 2) void gemm_tc(
    const float* __restrict__ A, const float* __restrict__ W,
    const float* __restrict__ bias, const float* __restrict__ resid,
    float* __restrict__ C, int M, int K, int N, int relu)
{
    extern __shared__ float gsm[];
    float* Asm[2] = {gsm, gsm + 128 * 36};
    float* Bsm[2] = {gsm + 2 * 128 * 36, gsm + 2 * 128 * 36 + 32 * 136};
    int tid = threadIdx.x;
    int lane = tid & 31, warp = tid >> 5;
    int wm = (warp >> 2) * 64;
    int wn = (warp & 3) * 32;
    size_t m0 = (size_t)blockIdx.y * 128, n0 = (size_t)blockIdx.x * 128;

    float acc[4][4][4] = {};

    int arow = tid >> 1, acq = (tid & 1) * 16;
    int brow = tid >> 3, bcq = (tid & 7) * 4;
    int r = lane >> 2, cg = lane & 3;

    const float* Abase = A + (m0 + arow) * K + acq;
    const float* Wbase = W + (size_t)brow * N + n0 + bcq;

#define GLOAD(s, k0)                                                           \
    do {                                                                       \
        _Pragma("unroll")                                                      \
        for (int j = 0; j < 4; j++)                                            \
            cpa16(sptr(&Asm[s][arow * 36 + acq + 4 * j]), Abase + (k0) + 4 * j); \
        _Pragma("unroll")                                                      \
        for (int j = 0; j < 4; j++)                                            \
            cpa16(sptr(&Bsm[s][brow * 136 + bcq + 32 * j]), Wbase + (size_t)(k0) * N + 32 * j); \
        asm volatile("cp.async.commit_group;\n" ::: "memory");                 \
    } while (0)

    GLOAD(0, 0);
    int st = 0;
    for (int k0 = 0; k0 < K; k0 += 32) {
        if (k0 + 32 < K) { GLOAD(st ^ 1, k0 + 32); asm volatile("cp.async.wait_group 1;\n" ::: "memory"); }
        else             { asm volatile("cp.async.wait_group 0;\n" ::: "memory"); }
        __syncthreads();
        const float* as = Asm[st];
        const float* bs = Bsm[st];
#pragma unroll
        for (int ks = 0; ks < 4; ks++) {
            int kb = ks * 8;
            uint32_t af[4][4], bf[4][2];
#pragma unroll
            for (int mi = 0; mi < 4; mi++) {
                int rb = wm + mi * 16;
                af[mi][0] = tf32u(as[(rb + r) * 36 + kb + cg]);
                af[mi][1] = tf32u(as[(rb + 8 + r) * 36 + kb + cg]);
                af[mi][2] = tf32u(as[(rb + r) * 36 + kb + 4 + cg]);
                af[mi][3] = tf32u(as[(rb + 8 + r) * 36 + kb + 4 + cg]);
            }
#pragma unroll
            for (int ni = 0; ni < 4; ni++) {
                bf[ni][0] = tf32u(bs[(kb + cg) * 136 + wn + ni * 8 + r]);
                bf[ni][1] = tf32u(bs[(kb + 4 + cg) * 136 + wn + ni * 8 + r]);
            }
#pragma unroll
            for (int mi = 0; mi < 4; mi++)
#pragma unroll
                for (int ni = 0; ni < 4; ni++)
                    mma_tf32(acc[mi][ni], af[mi], bf[ni]);
        }
        __syncthreads();
        st ^= 1;
    }

    int c2 = (lane & 3) * 2;
#pragma unroll
    for (int mi = 0; mi < 4; mi++) {
#pragma unroll
        for (int ni = 0; ni < 4; ni++) {
            size_t gm = m0 + wm + mi * 16 + r;
            size_t gn = n0 + wn + ni * 8 + c2;
            float b0v = bias[gn], b1v = bias[gn + 1];
            float v0 = acc[mi][ni][0] + b0v, v1 = acc[mi][ni][1] + b1v;
            float v2 = acc[mi][ni][2] + b0v, v3 = acc[mi][ni][3] + b1v;
            if (resid) {
                const float2 r0 = *(const float2*)(resid + gm * N + gn);
                const float2 r1 = *(const float2*)(resid + (gm + 8) * N + gn);
                v0 += r0.x; v1 += r0.y; v2 += r1.x; v3 += r1.y;
            }
            if (relu) {
                v0 = fmaxf(v0, 0.f); v1 = fmaxf(v1, 0.f);
                v2 = fmaxf(v2, 0.f); v3 = fmaxf(v3, 0.f);
            }
            *(float2*)(C + gm * N + gn) = make_float2(v0, v1);
            *(float2*)(C + (gm + 8) * N + gn) = make_float2(v2, v3);
        }
    }
}

// ---------------- tf32 tensor-core flash attention ---------------------------
// CTA: 128 q-rows of one (b,h); 256 threads = 8 warps x 16 rows.
// Qs[128][68], Ks[64][68]: fragment LDS hit bank==lane (conflict-free).
// Vb: V chunk 64x64 in 8x8-block k-major layout -> 64 blocks, stride 72.
// Ps[128][68]: per-warp private rows; only __syncwarp between store and PV.
// Pad-row semantics preserved: no chunk skipping; masked = -1e9 before exp.
#define FLASH_SMEM ((128*68 + 64*68 + 64*72 + 128*68) * 4)   // 105472 B
__global__ __launch_bounds__(256, 2) void flash_tc(
    const float* __restrict__ Q, const float* __restrict__ Kg,
    const float* __restrict__ Vg, float* __restrict__ O, int Tk,
    const int* __restrict__ target, int causal)
{
    extern __shared__ float fsm[];
    float* Qs = fsm;                          // [128][68]
    float* Ks = fsm + 128 * 68;               // [64][68]
    float* Vb = fsm + 128 * 68 + 64 * 68;     // [64 blocks][72]
    float* Ps = Vb + 64 * 72;                 // [128][68]

    int tid = threadIdx.x, lane = tid & 31, warp = tid >> 5;
    int z = blockIdx.y, b = z >> 3, h = z & 7;
    int tq0 = blockIdx.x * 128;
    int r = lane >> 2, c = lane & 3;
    int w16 = warp * 16;

    // load Q tile 128x64 (tf32-converted)
    {
        int row = tid >> 4, c4 = (tid & 15) * 4;
#pragma unroll
        for (int it = 0; it < 8; it++, row += 16) {
            float4 q4 = *(const float4*)(Q + (size_t)(b * T_ + tq0 + row) * D_ + h * DK_ + c4);
            q4.x = tf32r(q4.x); q4.y = tf32r(q4.y); q4.z = tf32r(q4.z); q4.w = tf32r(q4.w);
            *(float4*)&Qs[row * 68 + c4] = q4;
        }
    }

    int row0g = tq0 + w16 + r;        // global tq of this thread's first row
    int row1g = row0g + 8;
    bool rowok0 = causal ? (target[b * T_ + row0g] != 0) : true;
    bool rowok1 = causal ? (target[b * T_ + row1g] != 0) : true;

    float m0 = -1e30f, m1 = -1e30f, l0 = 0.f, l1 = 0.f;
    float o[8][4] = {};

    for (int kt0 = 0; kt0 < Tk; kt0 += 64) {
        // load K chunk -> Ks[tk][d]
        {
            int rowk = tid >> 4, c4 = (tid & 15) * 4;
#pragma unroll
            for (int it = 0; it < 4; it++, rowk += 16) {
                float4 k4 = *(const float4*)(Kg + (size_t)(b * Tk + kt0 + rowk) * D_ + h * DK_ + c4);
                k4.x = tf32r(k4.x); k4.y = tf32r(k4.y); k4.z = tf32r(k4.z); k4.w = tf32r(k4.w);
                *(float4*)&Ks[rowk * 68 + c4] = k4;
            }
        }
        // load V chunk transposed into block layout: element (tk, d) ->
        // Vb[((tk>>3)*8 + (d>>3))*72 + (tk&7)*8 + (d&7)]
        {
            int d = tid & 63, tk = tid >> 6;
#pragma unroll
            for (int it = 0; it < 16; it++, tk += 4) {
                float v = Vg[(size_t)(b * Tk + kt0 + tk) * D_ + h * DK_ + d];
                Vb[((tk >> 3) * 8 + (d >> 3)) * 72 + (tk & 7) * 8 + (d & 7)] = tf32r(v);
            }
        }
        __syncthreads();

        // S = Q K^T for this warp's 16 rows x 64 cols
        float sc[8][4] = {};
#pragma unroll
        for (int kb = 0; kb < 64; kb += 8) {
            uint32_t aa[4];
            aa[0] = __float_as_uint(Qs[(w16 + r) * 68 + kb + c]);
            aa[1] = __float_as_uint(Qs[(w16 + 8 + r) * 68 + kb + c]);
            aa[2] = __float_as_uint(Qs[(w16 + r) * 68 + kb + 4 + c]);
            aa[3] = __float_as_uint(Qs[(w16 + 8 + r) * 68 + kb + 4 + c]);
#pragma unroll
            for (int nt = 0; nt < 8; nt++) {
                uint32_t bb[2];
                bb[0] = __float_as_uint(Ks[(nt * 8 + r) * 68 + kb + c]);
                bb[1] = __float_as_uint(Ks[(nt * 8 + r) * 68 + kb + 4 + c]);
                mma_tf32(sc[nt], aa, bb);
            }
        }

        // scale + mask + online softmax (rows row0g, row1g)
        float mx0 = -1e30f, mx1 = -1e30f;
#pragma unroll
        for (int nt = 0; nt < 8; nt++) {
            int col0 = kt0 + nt * 8 + 2 * c;
            int col1 = col0 + 1;
            bool ok00 = !causal || (rowok0 && col0 <= row0g);
            bool ok01 = !causal || (rowok0 && col1 <= row0g);
            bool ok10 = !causal || (rowok1 && col0 <= row1g);
            bool ok11 = !causal || (rowok1 && col1 <= row1g);
            sc[nt][0] = ok00 ? sc[nt][0] * 0.125f : -1e9f;
            sc[nt][1] = ok01 ? sc[nt][1] * 0.125f : -1e9f;
            sc[nt][2] = ok10 ? sc[nt][2] * 0.125f : -1e9f;
            sc[nt][3] = ok11 ? sc[nt][3] * 0.125f : -1e9f;
            mx0 = fmaxf(mx0, fmaxf(sc[nt][0], sc[nt][1]));
            mx1 = fmaxf(mx1, fmaxf(sc[nt][2], sc[nt][3]));
        }
        mx0 = fmaxf(mx0, __shfl_xor_sync(0xffffffffu, mx0, 1));
        mx0 = fmaxf(mx0, __shfl_xor_sync(0xffffffffu, mx0, 2));
        mx1 = fmaxf(mx1, __shfl_xor_sync(0xffffffffu, mx1, 1));
        mx1 = fmaxf(mx1, __shfl_xor_sync(0xffffffffu, mx1, 2));
        float mn0 = fmaxf(m0, mx0), mn1 = fmaxf(m1, mx1);
        float al0 = expf(m0 - mn0), al1 = expf(m1 - mn1);
        m0 = mn0; m1 = mn1;
        float rs0 = 0.f, rs1 = 0.f;
#pragma unroll
        for (int nt = 0; nt < 8; nt++) {
            sc[nt][0] = expf(sc[nt][0] - mn0);
            sc[nt][1] = expf(sc[nt][1] - mn0);
            sc[nt][2] = expf(sc[nt][2] - mn1);
            sc[nt][3] = expf(sc[nt][3] - mn1);
            rs0 += sc[nt][0] + sc[nt][1];
            rs1 += sc[nt][2] + sc[nt][3];
        }
        rs0 += __shfl_xor_sync(0xffffffffu, rs0, 1);
        rs0 += __shfl_xor_sync(0xffffffffu, rs0, 2);
        rs1 += __shfl_xor_sync(0xffffffffu, rs1, 1);
        rs1 += __shfl_xor_sync(0xffffffffu, rs1, 2);
        l0 = l0 * al0 + rs0;
        l1 = l1 * al1 + rs1;
#pragma unroll
        for (int nt = 0; nt < 8; nt++) {
            o[nt][0] *= al0; o[nt][1] *= al0;
            o[nt][2] *= al1; o[nt][3] *= al1;
        }

        // stage P in smem (warp-private rows), tf32-converted
#pragma unroll
        for (int nt = 0; nt < 8; nt++) {
            *(float2*)&Ps[(w16 + r) * 68 + nt * 8 + 2 * c] =
                make_float2(tf32r(sc[nt][0]), tf32r(sc[nt][1]));
            *(float2*)&Ps[(w16 + 8 + r) * 68 + nt * 8 + 2 * c] =
                make_float2(tf32r(sc[nt][2]), tf32r(sc[nt][3]));
        }
        __syncwarp();

        // O += P V
#pragma unroll
        for (int kb = 0; kb < 64; kb += 8) {
            uint32_t aa[4];
            aa[0] = __float_as_uint(Ps[(w16 + r) * 68 + kb + c]);
            aa[1] = __float_as_uint(Ps[(w16 + 8 + r) * 68 + kb + c]);
            aa[2] = __float_as_uint(Ps[(w16 + r) * 68 + kb + 4 + c]);
            aa[3] = __float_as_uint(Ps[(w16 + 8 + r) * 68 + kb + 4 + c]);
            int kbi = kb >> 3;
#pragma unroll
            for (int nt = 0; nt < 8; nt++) {
                uint32_t bb[2];
                bb[0] = __float_as_uint(Vb[(kbi * 8 + nt) * 72 + c * 8 + r]);
                bb[1] = __float_as_uint(Vb[(kbi * 8 + nt) * 72 + 32 + c * 8 + r]);
                mma_tf32(o[nt], aa, bb);
            }
        }
        __syncthreads();   // all warps done with Ks/Vb before next chunk load
    }

    float inv0 = 1.0f / l0, inv1 = 1.0f / l1;
#pragma unroll
    for (int nt = 0; nt < 8; nt++) {
        size_t g0 = (size_t)(b * T_ + row0g) * D_ + h * DK_ + nt * 8 + 2 * c;
        *(float2*)(O + g0)          = make_float2(o[nt][0] * inv0, o[nt][1] * inv0);
        *(float2*)(O + g0 + 8 * D_) = make_float2(o[nt][2] * inv1, o[nt][3] * inv1);
    }
}

// ---------------- host orchestration ----------------------------------------
extern "C" void kernel_launch(void* const* d_in, const int* in_sizes, int n_in,
                              void* d_out, int out_size)
{
    (void)in_sizes; (void)n_in; (void)out_size;
    float *x, *nb, *q, *k, *v, *a, *f, *mk, *mv;
    cudaGetSymbolAddress((void**)&x,  g_x);
    cudaGetSymbolAddress((void**)&nb, g_n);
    cudaGetSymbolAddress((void**)&q,  g_q);
    cudaGetSymbolAddress((void**)&k,  g_k);
    cudaGetSymbolAddress((void**)&v,  g_v);
    cudaGetSymbolAddress((void**)&a,  g_a);
    cudaGetSymbolAddress((void**)&f,  g_f);
    cudaGetSymbolAddress((void**)&mk, g_mk);
    cudaGetSymbolAddress((void**)&mv, g_mv);

    static int attr_set = 0;
    if (!attr_set) {
        cudaFuncSetAttribute(gemm_tc,  cudaFuncAttributeMaxDynamicSharedMemorySize, GEMM_SMEM);
        cudaFuncSetAttribute(flash_tc, cudaFuncAttributeMaxDynamicSharedMemorySize, FLASH_SMEM);
        attr_set = 1;
    }

    // setup_inputs() dict order (verified R2: rel_err 1.2e-6)
    const int*   target = (const int*)  d_in[0];
    const float* memory = (const float*)d_in[1];
    const float* emb    = (const float*)d_in[2];
    const float* ln_g   = (const float*)d_in[3];
    const float* ln_b   = (const float*)d_in[4];
    const float* ff_w1  = (const float*)d_in[5];
    const float* ff_b1  = (const float*)d_in[6];
    const float* ff_w2  = (const float*)d_in[7];
    const float* ff_b2  = (const float*)d_in[8];
    const float* sa_wq  = (const float*)d_in[9];
    const float* sa_bq  = (const float*)d_in[10];
    const float* ca_wq  = (const float*)d_in[11];
    const float* ca_bq  = (const float*)d_in[12];
    const float* sa_wk  = (const float*)d_in[13];
    const float* sa_bk  = (const float*)d_in[14];
    const float* ca_wk  = (const float*)d_in[15];
    const float* ca_bk  = (const float*)d_in[16];
    const float* sa_wv  = (const float*)d_in[17];
    const float* sa_bv  = (const float*)d_in[18];
    const float* ca_wv  = (const float*)d_in[19];
    const float* ca_bv  = (const float*)d_in[20];
    const float* sa_wo  = (const float*)d_in[21];
    const float* sa_bo  = (const float*)d_in[22];
    const float* ca_wo  = (const float*)d_in[23];
    const float* ca_bo  = (const float*)d_in[24];

    embed_kernel<<<(NTOK * D_ + 255) / 256, 256>>>(target, emb, x);

    // cross-attn K/V of memory: computed ONCE (shared weights, static memory)
    gemm_tc<<<dim3(D_ / 128, NMEM / 128), 256, GEMM_SMEM>>>(memory, ca_wk, ca_bk, nullptr, mk, NMEM, D_, D_, 0);
    gemm_tc<<<dim3(D_ / 128, NMEM / 128), 256, GEMM_SMEM>>>(memory, ca_wv, ca_bv, nullptr, mv, NMEM, D_, D_, 0);

    dim3 gProj(D_ / 128, NTOK / 128);   // (4,64)
    dim3 gFF1 (FF_ / 128, NTOK / 128);  // (16,64)
    dim3 gFlash(T_ / 128, B_ * H_);     // (2,256)

    for (int stk = 0; stk < 3; stk++) {
        // ---- self attention ----
        ln_kernel<<<NTOK / 8, 256>>>(x, nb, ln_g, ln_b, NTOK);
        gemm_tc<<<gProj, 256, GEMM_SMEM>>>(nb, sa_wq, sa_bq, nullptr, q, NTOK, D_, D_, 0);
        gemm_tc<<<gProj, 256, GEMM_SMEM>>>(nb, sa_wk, sa_bk, nullptr, k, NTOK, D_, D_, 0);
        gemm_tc<<<gProj, 256, GEMM_SMEM>>>(nb, sa_wv, sa_bv, nullptr, v, NTOK, D_, D_, 0);
        flash_tc<<<gFlash, 256, FLASH_SMEM>>>(q, k, v, a, T_, target, 1);
        gemm_tc<<<gProj, 256, GEMM_SMEM>>>(a, sa_wo, sa_bo, x, x, NTOK, D_, D_, 0);

        // ---- cross attention ----
        ln_kernel<<<NTOK / 8, 256>>>(x, nb, ln_g, ln_b, NTOK);
        gemm_tc<<<gProj, 256, GEMM_SMEM>>>(nb, ca_wq, ca_bq, nullptr, q, NTOK, D_, D_, 0);
        flash_tc<<<gFlash, 256, FLASH_SMEM>>>(q, mk, mv, a, TM_, nullptr, 0);
        gemm_tc<<<gProj, 256, GEMM_SMEM>>>(a, ca_wo, ca_bo, x, x, NTOK, D_, D_, 0);

        // ---- feed forward ----
        ln_kernel<<<NTOK / 8, 256>>>(x, nb, ln_g, ln_b, NTOK);
        gemm_tc<<<gFF1, 256, GEMM_SMEM>>>(nb, ff_w1, ff_b1, nullptr, f, NTOK, D_, FF_, 1);
        gemm_tc<<<gProj, 256, GEMM_SMEM>>>(f, ff_w2, ff_b2, x, x, NTOK, FF_, D_, 0);
    }

    ln_kernel<<<NTOK / 8, 256>>>(x, (float*)d_out, ln_g, ln_b, NTOK);
}